// round 13
// baseline (speedup 1.0000x reference)
#include <cuda_runtime.h>
#include <cuda_fp16.h>
#include <math.h>
#include <stdint.h>

// ---------------- problem constants ----------------
#define NPTS    524288
#define GRID_D  300
#define NCOMP   36
#define CPAD    64        // channel dim padded to 64 halves = 128B (one aligned line per corner)
#define SDF_DIM 256
#define OUT_CH  129
#define K1      144       // GEMM1 K (129 used + pad), 9 k-steps
#define AP      152       // A / W1 smem pitch in halves (304B -> conflict-free ldmatrix)
#define N2P     136       // GEMM2 N padded (129 used), 17 n-tiles of 8
#define K2      256       // GEMM2 K, 16 k-steps
#define HP      264       // H / W2 smem pitch in halves (528B -> conflict-free)
#define TILE_M  96
#define NTILES  ((NPTS + TILE_M - 1) / TILE_M)   // 5462 (last tile partial: 32 pts)
#define NTHR    384

// ---------------- smem layout (bytes) ----------------
#define SM_A   0
#define SM_H   (SM_A + TILE_M * AP * 2)       // 29184
#define SM_W1  (SM_H + TILE_M * HP * 2)       // +50688 = 79872
#define SM_W2  (SM_W1 + SDF_DIM * AP * 2)     // +77824 = 157696
#define SM_B2  (SM_W2 + N2P * HP * 2)         // +71808 = 229504
#define SM_TOTAL (SM_B2 + N2P * 4)            // 230048

// ---------------- scratch globals ----------------
__device__ __align__(16) __half g_planesTh[3 * GRID_D * GRID_D * CPAD]; // [p][y][x][c64] fp16 (c>=36 zero)
__device__ __align__(16) __half g_linesTh[3 * GRID_D * CPAD];           // [p][z][c64] fp16 (c>=36 zero)
__device__ __align__(16) __half g_w1h[SDF_DIM * K1];                    // [j][k] (permuted, bias row k=129)
__device__ __align__(16) __half g_w2h[N2P * K2];                        // [o][j] (rows >=129 zero)

// ---------------- PTX helpers (sm_80-era, compile on plain sm_103) ----------------
__device__ __forceinline__ uint32_t smem_to_u32(const void* p) {
    uint32_t a;
    asm("{ .reg .u64 t; cvta.to.shared.u64 t, %1; cvt.u32.u64 %0, t; }" : "=r"(a) : "l"(p));
    return a;
}
__device__ __forceinline__ void ldm_x4(uint32_t& r0, uint32_t& r1, uint32_t& r2, uint32_t& r3, uint32_t addr) {
    asm volatile("ldmatrix.sync.aligned.m8n8.x4.shared.b16 {%0,%1,%2,%3}, [%4];"
                 : "=r"(r0), "=r"(r1), "=r"(r2), "=r"(r3) : "r"(addr));
}
__device__ __forceinline__ void ldm_x2(uint32_t& r0, uint32_t& r1, uint32_t addr) {
    asm volatile("ldmatrix.sync.aligned.m8n8.x2.shared.b16 {%0,%1}, [%2];"
                 : "=r"(r0), "=r"(r1) : "r"(addr));
}
__device__ __forceinline__ void mma16816(float* c, const uint32_t* a, uint32_t b0, uint32_t b1) {
    asm volatile("mma.sync.aligned.m16n8k16.row.col.f32.f16.f16.f32 "
                 "{%0,%1,%2,%3}, {%4,%5,%6,%7}, {%8,%9}, {%0,%1,%2,%3};"
                 : "+f"(c[0]), "+f"(c[1]), "+f"(c[2]), "+f"(c[3])
                 : "r"(a[0]), "r"(a[1]), "r"(a[2]), "r"(a[3]), "r"(b0), "r"(b1));
}

// ---------------- preprocess: planes -> fp16 [3][300][300][64] (pad ch zeroed) ----------------
__global__ void transpose_planes_kernel(const float* __restrict__ planes) {
    int b = blockIdx.x;
    int xt = b % 10;
    int rest = b / 10;
    int y = rest % GRID_D;
    int p = rest / GRID_D;
    int x0 = xt * 32;
    __shared__ float tile[NCOMP][33];
    for (int idx = threadIdx.x; idx < NCOMP * 32; idx += blockDim.x) {
        int c = idx >> 5, xx = idx & 31;
        if (x0 + xx < GRID_D)
            tile[c][xx] = planes[((p * NCOMP + c) * GRID_D + y) * GRID_D + x0 + xx];
    }
    __syncthreads();
    for (int idx = threadIdx.x; idx < 32 * CPAD; idx += blockDim.x) {
        int xx = idx / CPAD, c = idx % CPAD;
        if (x0 + xx < GRID_D)
            g_planesTh[((size_t)(p * GRID_D + y) * GRID_D + (x0 + xx)) * CPAD + c] =
                __float2half_rn((c < NCOMP) ? tile[c][xx] : 0.0f);
    }
}

// ---------------- preprocess: fp16 weights (permuted, bias-folded) + fp16 lines ----------------
// A channel order: k 0..107 = feat (orig mlp_in 21..128), k 108..128 = embed (orig 0..20),
//                  k 129 = bias row (A=1, W1=b1), k 130..143 = 0.
__global__ void prep_small_kernel(const float* __restrict__ w1, const float* __restrict__ b1,
                                  const float* __restrict__ w2,
                                  const float* __restrict__ lines) {
    int i = blockIdx.x * blockDim.x + threadIdx.x;
    const int W1N = SDF_DIM * K1;        // 36864
    const int W2N = N2P * K2;            // 34816
    const int LNT = 3 * GRID_D * CPAD;   // 57600
    if (i < W1N) {
        int j = i / K1, k = i % K1;
        float v = 0.0f;
        if (k < 108)       v = w1[j * OUT_CH + 21 + k];
        else if (k < 129)  v = w1[j * OUT_CH + (k - 108)];
        else if (k == 129) v = b1[j];
        g_w1h[i] = __float2half_rn(v);
    } else if (i < W1N + W2N) {
        int t = i - W1N;
        int o = t / K2, j = t % K2;
        g_w2h[t] = __float2half_rn((o < OUT_CH) ? w2[o * SDF_DIM + j] : 0.0f);
    } else if (i < W1N + W2N + LNT) {
        int t = i - W1N - W2N;
        int c = t % CPAD;
        int z = (t / CPAD) % GRID_D;
        int p = t / (CPAD * GRID_D);
        g_linesTh[t] = __float2half_rn((c < NCOMP) ? lines[(p * NCOMP + c) * GRID_D + z] : 0.0f);
    }
}

// ---------------- activation: softplus(100u)/100 ----------------
__device__ __forceinline__ float actf(float u) {
    float t = 100.0f * u;
    return (fmaxf(t, 0.0f) + __logf(1.0f + __expf(-fabsf(t)))) * 0.01f;
}

union U4H { uint4 u; __half2 h[4]; };

// ---------------- persistent fused main kernel ----------------
__global__ __launch_bounds__(NTHR)
void tensosdf_main_kernel(const float* __restrict__ xyz,
                          const float* __restrict__ b2,
                          float* __restrict__ out) {
    extern __shared__ char smem[];
    const uint32_t su = smem_to_u32(smem);
    const int tid  = threadIdx.x;
    const int wid  = tid >> 5;
    const int lane = tid & 31;
    float* b2s = (float*)(smem + SM_B2);

    // ---- stage weights into smem once per CTA ----
    {
        __half* sW1 = (__half*)(smem + SM_W1);
        __half* sW2 = (__half*)(smem + SM_W2);
        for (int i = tid; i < SDF_DIM * K1; i += NTHR) {
            int j = i / K1, k = i % K1;
            sW1[j * AP + k] = g_w1h[i];
        }
        for (int i = tid; i < N2P * K2; i += NTHR) {
            int o = i >> 8, j = i & 255;
            sW2[o * HP + j] = g_w2h[i];
        }
        if (tid < N2P) b2s[tid] = (tid < OUT_CH) ? b2[tid] : 0.0f;
    }
    __syncthreads();

    const int mw = wid >> 2;   // 0..2 : 32-point m-slab
    const int nw = wid & 3;    // 0..3 : n-slab
    const int g  = lane >> 2;  // mma C-frag row group
    const int tq = lane & 3;   // mma C-frag col pair

    const int a_row  = (lane & 15);
    const int a_koff = (lane >> 4) * 8;                       // halves
    const int b4_row = (lane & 7) + ((lane >> 4) & 1) * 8;    // x4 B: n16 rows
    const int b_koff = ((lane >> 3) & 1) * 8;                 // halves

    const int lc = lane & 7;   // 8-channel chunk within corner line
    const int kt = lane >> 3;  // task slot within round (0..3)

    for (int tile = blockIdx.x; tile < NTILES; tile += gridDim.x) {
        const int pt0 = tile * TILE_M;

        // ======== Phase A: cooperative gather (all 12 warps) + embed ========
        #pragma unroll
        for (int r = 0; r < 6; r++) {
            const int T = wid * 24 + r * 4 + kt;
            const int point = T / 3;
            const int pl    = T - point * 3;
            if (lc < 5) {
                int gp = pt0 + point;
                if (gp >= NPTS) gp = NPTS - 1;
                float x = xyz[gp * 3 + 0];
                float y = xyz[gp * 3 + 1];
                float z = xyz[gp * 3 + 2];
                float sx, sy, sz;
                if (pl == 0)      { sx = x; sy = y; sz = z; }
                else if (pl == 1) { sx = x; sy = z; sz = y; }
                else              { sx = y; sy = z; sz = x; }
                const float HALF = 0.5f * (GRID_D - 1);
                float fx = (sx + 1.0f) * HALF;
                float fy = (sy + 1.0f) * HALF;
                float fz = (sz + 1.0f) * HALF;
                int x0 = min(max((int)floorf(fx), 0), GRID_D - 2);
                int y0 = min(max((int)floorf(fy), 0), GRID_D - 2);
                int z0 = min(max((int)floorf(fz), 0), GRID_D - 2);
                float tx = fx - (float)x0;
                float ty = fy - (float)y0;
                float tz = fz - (float)z0;
                float w00 = (1.0f - tx) * (1.0f - ty);
                float w01 = tx * (1.0f - ty);
                float w10 = (1.0f - tx) * ty;
                float w11 = tx * ty;

                const __half* P = g_planesTh + ((size_t)(pl * GRID_D + y0) * GRID_D + x0) * CPAD + lc * 8;
                const __half* L = g_linesTh + ((size_t)(pl * GRID_D + z0)) * CPAD + lc * 8;
                U4H v00, v01, v10, v11, l0v, l1v;
                v00.u = *(const uint4*)(P);
                v01.u = *(const uint4*)(P + CPAD);
                v10.u = *(const uint4*)(P + GRID_D * CPAD);
                v11.u = *(const uint4*)(P + GRID_D * CPAD + CPAD);
                l0v.u = *(const uint4*)(L);
                l1v.u = *(const uint4*)(L + CPAD);

                uint32_t res[4];
                #pragma unroll
                for (int i = 0; i < 4; i++) {
                    float2 a00 = __half22float2(v00.h[i]);
                    float2 a01 = __half22float2(v01.h[i]);
                    float2 a10 = __half22float2(v10.h[i]);
                    float2 a11 = __half22float2(v11.h[i]);
                    float2 b0  = __half22float2(l0v.h[i]);
                    float2 b1  = __half22float2(l1v.h[i]);
                    float ra = (a00.x * w00 + a01.x * w01 + a10.x * w10 + a11.x * w11)
                             * (b0.x + (b1.x - b0.x) * tz);
                    float rb = (a00.y * w00 + a01.y * w01 + a10.y * w10 + a11.y * w11)
                             * (b0.y + (b1.y - b0.y) * tz);
                    __half2 hh = __floats2half2_rn(ra, rb);
                    res[i] = *(uint32_t*)&hh;
                }
                char* dst = smem + SM_A + point * (AP * 2) + (pl * NCOMP + lc * 8) * 2;
                uint2 lo; lo.x = res[0]; lo.y = res[1];
                *(uint2*)dst = lo;
                if (lc < 4) {
                    uint2 hi; hi.x = res[2]; hi.y = res[3];
                    *(uint2*)(dst + 8) = hi;
                }
            }
        }
        // embed: one point per thread (tid < 96)
        if (tid < TILE_M) {
            int gp = pt0 + tid;
            if (gp >= NPTS) gp = NPTS - 1;
            float vx = xyz[gp * 3 + 0];
            float vy = xyz[gp * 3 + 1];
            float vz = xyz[gp * 3 + 2];
            float e[22];
            e[0] = vx; e[1] = vy; e[2] = vz;
            #pragma unroll
            for (int d = 0; d < 3; d++) {
                float v = (d == 0) ? vx : (d == 1) ? vy : vz;
                #pragma unroll
                for (int f = 0; f < 3; f++) {
                    float s, c;
                    sincosf(v * (float)(1 << f), &s, &c);
                    e[3 + d * 3 + f]  = s;
                    e[12 + d * 3 + f] = c;
                }
            }
            e[21] = 1.0f;  // bias row at k=129
            char* dst = smem + SM_A + tid * (AP * 2) + 108 * 2;
            #pragma unroll
            for (int i = 0; i < 18; i++) {
                int k0 = 108 + 2 * i;
                float lo = (k0 <= 129) ? e[k0 - 108] : 0.0f;
                float hi = (k0 + 1 <= 129) ? e[k0 + 1 - 108] : 0.0f;
                __half2 h = __floats2half2_rn(lo, hi);
                *(uint32_t*)(dst + i * 4) = *(uint32_t*)&h;
            }
        }
        __syncthreads();   // S1: A ready (also orders H(t) reads vs H(t+1) writes)

        // ======== GEMM1: H = act(A @ W1^T), jt-pairs with x4 W1 loads ========
        {
            uint32_t Af[2][9][4];
            const uint32_t a_base = su + SM_A + (uint32_t)(mw * 32 + a_row) * (AP * 2) + (uint32_t)a_koff * 2;
            #pragma unroll
            for (int t = 0; t < 2; t++)
                #pragma unroll
                for (int s = 0; s < 9; s++)
                    ldm_x4(Af[t][s][0], Af[t][s][1], Af[t][s][2], Af[t][s][3],
                           a_base + (uint32_t)t * 16 * (AP * 2) + (uint32_t)s * 32);

            const uint32_t w1b = su + SM_W1 + (uint32_t)(nw * 64 + b4_row) * (AP * 2) + (uint32_t)b_koff * 2;
            #pragma unroll
            for (int jp = 0; jp < 4; jp++) {
                float acc[2][2][4] = {{{0,0,0,0},{0,0,0,0}},{{0,0,0,0},{0,0,0,0}}};  // [t][jt-in-pair][4]
                #pragma unroll
                for (int s = 0; s < 9; s++) {
                    uint32_t w0, w1v, w2v, w3v;
                    ldm_x4(w0, w1v, w2v, w3v, w1b + (uint32_t)jp * 16 * (AP * 2) + (uint32_t)s * 32);
                    mma16816(acc[0][0], Af[0][s], w0, w1v);
                    mma16816(acc[0][1], Af[0][s], w2v, w3v);
                    mma16816(acc[1][0], Af[1][s], w0, w1v);
                    mma16816(acc[1][1], Af[1][s], w2v, w3v);
                }
                #pragma unroll
                for (int t = 0; t < 2; t++) {
                    #pragma unroll
                    for (int jj = 0; jj < 2; jj++) {
                        __half2 hlo = __floats2half2_rn(actf(acc[t][jj][0]), actf(acc[t][jj][1]));
                        __half2 hhi = __floats2half2_rn(actf(acc[t][jj][2]), actf(acc[t][jj][3]));
                        char* hp0 = smem + SM_H + (mw * 32 + t * 16 + g) * (HP * 2)
                                  + (nw * 64 + jp * 16 + jj * 8 + tq * 2) * 2;
                        *(uint32_t*)hp0 = *(uint32_t*)&hlo;
                        *(uint32_t*)(hp0 + 8 * (HP * 2)) = *(uint32_t*)&hhi;
                    }
                }
            }
        }
        __syncthreads();   // S2: H ready (also ends all A reads before next gather)

        // ======== GEMM2: out = H @ W2^T + b2 ========
        // n-split: warp nw covers cols [nw*32, nw*32+32) (2 jt-pairs); nw==0 also jt16 (col 128).
        // H and W2 fragments streamed per k-step; each byte read ONCE per warp.
        {
            const uint32_t h_base = su + SM_H + (uint32_t)(mw * 32 + a_row) * (HP * 2) + (uint32_t)a_koff * 2;
            const uint32_t w2b  = su + SM_W2 + (uint32_t)(nw * 32 + b4_row) * (HP * 2) + (uint32_t)b_koff * 2;
            const uint32_t w2b16 = su + SM_W2 + (uint32_t)(128 + (lane & 7)) * (HP * 2) + (uint32_t)b_koff * 2;

            float acc[2][2][2][4];   // [t][pair][jt-in-pair][4]
            #pragma unroll
            for (int t = 0; t < 2; t++)
                #pragma unroll
                for (int p2 = 0; p2 < 2; p2++)
                    #pragma unroll
                    for (int jj = 0; jj < 2; jj++)
                        { acc[t][p2][jj][0]=0; acc[t][p2][jj][1]=0; acc[t][p2][jj][2]=0; acc[t][p2][jj][3]=0; }
            float a16[2][4] = {{0,0,0,0},{0,0,0,0}};   // jt16 (nw==0 only)

            #pragma unroll
            for (int s = 0; s < 16; s++) {
                uint32_t h0[4], h1[4];
                ldm_x4(h0[0], h0[1], h0[2], h0[3], h_base + (uint32_t)s * 32);
                ldm_x4(h1[0], h1[1], h1[2], h1[3], h_base + 16 * (HP * 2) + (uint32_t)s * 32);
                #pragma unroll
                for (int p2 = 0; p2 < 2; p2++) {
                    uint32_t w0, w1v, w2v, w3v;
                    ldm_x4(w0, w1v, w2v, w3v, w2b + (uint32_t)p2 * 16 * (HP * 2) + (uint32_t)s * 32);
                    mma16816(acc[0][p2][0], h0, w0, w1v);
                    mma16816(acc[0][p2][1], h0, w2v, w3v);
                    mma16816(acc[1][p2][0], h1, w0, w1v);
                    mma16816(acc[1][p2][1], h1, w2v, w3v);
                }
                if (nw == 0) {
                    uint32_t b0, b1v;
                    ldm_x2(b0, b1v, w2b16 + (uint32_t)s * 32);
                    mma16816(a16[0], h0, b0, b1v);
                    mma16816(a16[1], h1, b0, b1v);
                }
            }

            // epilogue: + b2 -> global (main cols 0..127: all in-range, no oc checks)
            #pragma unroll
            for (int t = 0; t < 2; t++) {
                const int pr = pt0 + mw * 32 + t * 16 + g;
                const bool ok0 = (pr < NPTS);
                const bool ok8 = (pr + 8 < NPTS);
                #pragma unroll
                for (int p2 = 0; p2 < 2; p2++) {
                    #pragma unroll
                    for (int jj = 0; jj < 2; jj++) {
                        const int oc = nw * 32 + p2 * 16 + jj * 8 + tq * 2;
                        const float* a = acc[t][p2][jj];
                        if (ok0) {
                            out[(size_t)pr * OUT_CH + oc]     = a[0] + b2s[oc];
                            out[(size_t)pr * OUT_CH + oc + 1] = a[1] + b2s[oc + 1];
                        }
                        if (ok8) {
                            out[(size_t)(pr + 8) * OUT_CH + oc]     = a[2] + b2s[oc];
                            out[(size_t)(pr + 8) * OUT_CH + oc + 1] = a[3] + b2s[oc + 1];
                        }
                    }
                }
                if (nw == 0 && tq == 0) {   // col 128 (129..135 are pad)
                    if (ok0) out[(size_t)pr * OUT_CH + 128]       = a16[t][0] + b2s[128];
                    if (ok8) out[(size_t)(pr + 8) * OUT_CH + 128] = a16[t][2] + b2s[128];
                }
            }
        }
        // no 3rd barrier: next S1 provides the H(t)-read / H(t+1)-write ordering,
        // and gather(t+1) only writes A, which no warp touches after S2.
    }
}

// ---------------- launch ----------------
extern "C" void kernel_launch(void* const* d_in, const int* in_sizes, int n_in,
                              void* d_out, int out_size) {
    const float* xyz    = (const float*)d_in[0];
    const float* planes = (const float*)d_in[1];
    const float* lines  = (const float*)d_in[2];
    const float* w1     = (const float*)d_in[3];
    const float* b1     = (const float*)d_in[4];
    const float* w2     = (const float*)d_in[5];
    const float* b2     = (const float*)d_in[6];
    float* out = (float*)d_out;

    int nsm = 148;
    cudaDeviceGetAttribute(&nsm, cudaDevAttrMultiProcessorCount, 0);

    cudaFuncSetAttribute(tensosdf_main_kernel,
                         cudaFuncAttributeMaxDynamicSharedMemorySize, SM_TOTAL);

    transpose_planes_kernel<<<3 * GRID_D * 10, 256>>>(planes);

    const int prep_total = SDF_DIM * K1 + N2P * K2 + 3 * GRID_D * CPAD;
    prep_small_kernel<<<(prep_total + 255) / 256, 256>>>(w1, b1, w2, lines);

    tensosdf_main_kernel<<<nsm, NTHR, SM_TOTAL>>>(xyz, b2, out);
}

// round 14
// speedup vs baseline: 1.5684x; 1.5684x over previous
#include <cuda_runtime.h>
#include <cuda_fp16.h>
#include <math.h>
#include <stdint.h>

// ---------------- problem constants ----------------
#define NPTS    524288
#define GRID_D  300
#define NCOMP   36
#define CPAD    64        // channel dim padded to 64 halves = 128B (one aligned line per corner)
#define SDF_DIM 256
#define OUT_CH  129
#define K1      144       // GEMM1 K (129 used + pad), 9 k-steps
#define AP      152       // A / W1 smem pitch in halves (304B -> conflict-free ldmatrix)
#define N2P     136       // GEMM2 N padded (129 used), 17 n-tiles of 8
#define K2      256       // GEMM2 K, 16 k-steps
#define HP      264       // H / W2 smem pitch in halves (528B -> conflict-free)
#define TILE_M  96
#define NTILES  ((NPTS + TILE_M - 1) / TILE_M)   // 5462 (last tile partial: 32 pts)
#define NTHR    384

// ---------------- smem layout (bytes) ----------------
#define SM_A   0
#define SM_H   (SM_A + TILE_M * AP * 2)       // 29184
#define SM_W1  (SM_H + TILE_M * HP * 2)       // +50688 = 79872
#define SM_W2  (SM_W1 + SDF_DIM * AP * 2)     // +77824 = 157696
#define SM_B2  (SM_W2 + N2P * HP * 2)         // +71808 = 229504
#define SM_TOTAL (SM_B2 + N2P * 4)            // 230048

// ---------------- scratch globals ----------------
__device__ __align__(16) __half g_planesTh[3 * GRID_D * GRID_D * CPAD]; // [p][y][x][c64] fp16 (c>=36 zero)
__device__ __align__(16) __half g_linesTh[3 * GRID_D * CPAD];           // [p][z][c64] fp16 (c>=36 zero)
__device__ __align__(16) __half g_w1h[SDF_DIM * K1];                    // [j][k] (permuted, bias row k=129)
__device__ __align__(16) __half g_w2h[N2P * K2];                        // [o][j] (rows >=129 zero)

// ---------------- PTX helpers (sm_80-era, compile on plain sm_103) ----------------
__device__ __forceinline__ uint32_t smem_to_u32(const void* p) {
    uint32_t a;
    asm("{ .reg .u64 t; cvta.to.shared.u64 t, %1; cvt.u32.u64 %0, t; }" : "=r"(a) : "l"(p));
    return a;
}
__device__ __forceinline__ void ldm_x4(uint32_t& r0, uint32_t& r1, uint32_t& r2, uint32_t& r3, uint32_t addr) {
    asm volatile("ldmatrix.sync.aligned.m8n8.x4.shared.b16 {%0,%1,%2,%3}, [%4];"
                 : "=r"(r0), "=r"(r1), "=r"(r2), "=r"(r3) : "r"(addr));
}
__device__ __forceinline__ void ldm_x2(uint32_t& r0, uint32_t& r1, uint32_t addr) {
    asm volatile("ldmatrix.sync.aligned.m8n8.x2.shared.b16 {%0,%1}, [%2];"
                 : "=r"(r0), "=r"(r1) : "r"(addr));
}
__device__ __forceinline__ void mma16816(float* c, const uint32_t* a, uint32_t b0, uint32_t b1) {
    asm volatile("mma.sync.aligned.m16n8k16.row.col.f32.f16.f16.f32 "
                 "{%0,%1,%2,%3}, {%4,%5,%6,%7}, {%8,%9}, {%0,%1,%2,%3};"
                 : "+f"(c[0]), "+f"(c[1]), "+f"(c[2]), "+f"(c[3])
                 : "r"(a[0]), "r"(a[1]), "r"(a[2]), "r"(a[3]), "r"(b0), "r"(b1));
}

// ---------------- preprocess: planes -> fp16 [3][300][300][64] (pad ch zeroed) ----------------
// vectorized: one uint4 (8 halves) store per thread, single pass
__global__ void transpose_planes_kernel(const float* __restrict__ planes) {
    int b = blockIdx.x;
    int xt = b % 10;
    int rest = b / 10;
    int y = rest % GRID_D;
    int p = rest / GRID_D;
    int x0 = xt * 32;
    __shared__ float tile[NCOMP][33];
    for (int idx = threadIdx.x; idx < NCOMP * 32; idx += blockDim.x) {
        int c = idx >> 5, xx = idx & 31;
        if (x0 + xx < GRID_D)
            tile[c][xx] = planes[((p * NCOMP + c) * GRID_D + y) * GRID_D + x0 + xx];
    }
    __syncthreads();
    {
        int xx = threadIdx.x >> 3;        // 0..31
        int cg = threadIdx.x & 7;         // 8-half group
        if (x0 + xx < GRID_D) {
            union { uint4 u; __half h[8]; } v;
            #pragma unroll
            for (int i = 0; i < 8; i++) {
                int c = cg * 8 + i;
                v.h[i] = __float2half_rn((c < NCOMP) ? tile[c][xx] : 0.0f);
            }
            *(uint4*)(g_planesTh + ((size_t)(p * GRID_D + y) * GRID_D + (x0 + xx)) * CPAD + cg * 8) = v.u;
        }
    }
}

// ---------------- preprocess: fp16 weights (permuted, bias-folded) + fp16 lines ----------------
// A channel order: k 0..107 = feat (orig mlp_in 21..128), k 108..128 = embed (orig 0..20),
//                  k 129 = bias row (A=1, W1=b1), k 130..143 = 0.
__global__ void prep_small_kernel(const float* __restrict__ w1, const float* __restrict__ b1,
                                  const float* __restrict__ w2,
                                  const float* __restrict__ lines) {
    int i = blockIdx.x * blockDim.x + threadIdx.x;
    const int W1N = SDF_DIM * K1;        // 36864
    const int W2N = N2P * K2;            // 34816
    const int LNT = 3 * GRID_D * CPAD;   // 57600
    if (i < W1N) {
        int j = i / K1, k = i % K1;
        float v = 0.0f;
        if (k < 108)       v = w1[j * OUT_CH + 21 + k];
        else if (k < 129)  v = w1[j * OUT_CH + (k - 108)];
        else if (k == 129) v = b1[j];
        g_w1h[i] = __float2half_rn(v);
    } else if (i < W1N + W2N) {
        int t = i - W1N;
        int o = t / K2, j = t % K2;
        g_w2h[t] = __float2half_rn((o < OUT_CH) ? w2[o * SDF_DIM + j] : 0.0f);
    } else if (i < W1N + W2N + LNT) {
        int t = i - W1N - W2N;
        int c = t % CPAD;
        int z = (t / CPAD) % GRID_D;
        int p = t / (CPAD * GRID_D);
        g_linesTh[t] = __float2half_rn((c < NCOMP) ? lines[(p * NCOMP + c) * GRID_D + z] : 0.0f);
    }
}

// ---------------- activation: softplus(100u)/100 ----------------
__device__ __forceinline__ float actf(float u) {
    float t = 100.0f * u;
    return (fmaxf(t, 0.0f) + __logf(1.0f + __expf(-fabsf(t)))) * 0.01f;
}

union U4H { uint4 u; __half2 h[4]; };

// ---------------- persistent fused main kernel ----------------
__global__ __launch_bounds__(NTHR)
void tensosdf_main_kernel(const float* __restrict__ xyz,
                          const float* __restrict__ b2,
                          float* __restrict__ out) {
    extern __shared__ char smem[];
    const uint32_t su = smem_to_u32(smem);
    const int tid  = threadIdx.x;
    const int wid  = tid >> 5;
    const int lane = tid & 31;
    float* b2s = (float*)(smem + SM_B2);

    // ---- stage weights into smem once per CTA ----
    {
        __half* sW1 = (__half*)(smem + SM_W1);
        __half* sW2 = (__half*)(smem + SM_W2);
        for (int i = tid; i < SDF_DIM * K1; i += NTHR) {
            int j = i / K1, k = i % K1;
            sW1[j * AP + k] = g_w1h[i];
        }
        for (int i = tid; i < N2P * K2; i += NTHR) {
            int o = i >> 8, j = i & 255;
            sW2[o * HP + j] = g_w2h[i];
        }
        if (tid < N2P) b2s[tid] = (tid < OUT_CH) ? b2[tid] : 0.0f;
    }
    __syncthreads();

    const int mw = wid >> 2;   // 0..2 : 32-point m-slab
    const int nw = wid & 3;    // 0..3 : n-slab
    const int g  = lane >> 2;  // mma C-frag row group
    const int tq = lane & 3;   // mma C-frag col pair

    const int a_row  = (lane & 15);
    const int a_koff = (lane >> 4) * 8;          // halves
    const int b_row  = (lane & 7);
    const int b_koff = ((lane >> 3) & 1) * 8;    // halves

    const int lc = lane & 7;   // 8-channel chunk within corner line
    const int kt = lane >> 3;  // task slot within round (0..3)

    for (int tile = blockIdx.x; tile < NTILES; tile += gridDim.x) {
        const int pt0 = tile * TILE_M;

        // ======== Phase A: cooperative gather (all 12 warps) + embed ========
        #pragma unroll
        for (int r = 0; r < 6; r++) {
            const int T = wid * 24 + r * 4 + kt;
            const int point = T / 3;
            const int pl    = T - point * 3;
            if (lc < 5) {
                int gp = pt0 + point;
                if (gp >= NPTS) gp = NPTS - 1;
                float x = xyz[gp * 3 + 0];
                float y = xyz[gp * 3 + 1];
                float z = xyz[gp * 3 + 2];
                float sx, sy, sz;
                if (pl == 0)      { sx = x; sy = y; sz = z; }
                else if (pl == 1) { sx = x; sy = z; sz = y; }
                else              { sx = y; sy = z; sz = x; }
                const float HALF = 0.5f * (GRID_D - 1);
                float fx = (sx + 1.0f) * HALF;
                float fy = (sy + 1.0f) * HALF;
                float fz = (sz + 1.0f) * HALF;
                int x0 = min(max((int)floorf(fx), 0), GRID_D - 2);
                int y0 = min(max((int)floorf(fy), 0), GRID_D - 2);
                int z0 = min(max((int)floorf(fz), 0), GRID_D - 2);
                float tx = fx - (float)x0;
                float ty = fy - (float)y0;
                float tz = fz - (float)z0;
                float w00 = (1.0f - tx) * (1.0f - ty);
                float w01 = tx * (1.0f - ty);
                float w10 = (1.0f - tx) * ty;
                float w11 = tx * ty;

                const __half* P = g_planesTh + ((size_t)(pl * GRID_D + y0) * GRID_D + x0) * CPAD + lc * 8;
                const __half* L = g_linesTh + ((size_t)(pl * GRID_D + z0)) * CPAD + lc * 8;
                U4H v00, v01, v10, v11, l0v, l1v;
                v00.u = *(const uint4*)(P);
                v01.u = *(const uint4*)(P + CPAD);
                v10.u = *(const uint4*)(P + GRID_D * CPAD);
                v11.u = *(const uint4*)(P + GRID_D * CPAD + CPAD);
                l0v.u = *(const uint4*)(L);
                l1v.u = *(const uint4*)(L + CPAD);

                uint32_t res[4];
                #pragma unroll
                for (int i = 0; i < 4; i++) {
                    float2 a00 = __half22float2(v00.h[i]);
                    float2 a01 = __half22float2(v01.h[i]);
                    float2 a10 = __half22float2(v10.h[i]);
                    float2 a11 = __half22float2(v11.h[i]);
                    float2 b0  = __half22float2(l0v.h[i]);
                    float2 b1  = __half22float2(l1v.h[i]);
                    float ra = (a00.x * w00 + a01.x * w01 + a10.x * w10 + a11.x * w11)
                             * (b0.x + (b1.x - b0.x) * tz);
                    float rb = (a00.y * w00 + a01.y * w01 + a10.y * w10 + a11.y * w11)
                             * (b0.y + (b1.y - b0.y) * tz);
                    __half2 hh = __floats2half2_rn(ra, rb);
                    res[i] = *(uint32_t*)&hh;
                }
                char* dst = smem + SM_A + point * (AP * 2) + (pl * NCOMP + lc * 8) * 2;
                uint2 lo; lo.x = res[0]; lo.y = res[1];
                *(uint2*)dst = lo;
                if (lc < 4) {
                    uint2 hi; hi.x = res[2]; hi.y = res[3];
                    *(uint2*)(dst + 8) = hi;
                }
            }
        }
        // embed: one point per thread (tid < 96)
        if (tid < TILE_M) {
            int gp = pt0 + tid;
            if (gp >= NPTS) gp = NPTS - 1;
            float vx = xyz[gp * 3 + 0];
            float vy = xyz[gp * 3 + 1];
            float vz = xyz[gp * 3 + 2];
            float e[22];
            e[0] = vx; e[1] = vy; e[2] = vz;
            #pragma unroll
            for (int d = 0; d < 3; d++) {
                float v = (d == 0) ? vx : (d == 1) ? vy : vz;
                #pragma unroll
                for (int f = 0; f < 3; f++) {
                    float s, c;
                    sincosf(v * (float)(1 << f), &s, &c);
                    e[3 + d * 3 + f]  = s;
                    e[12 + d * 3 + f] = c;
                }
            }
            e[21] = 1.0f;  // bias row at k=129
            char* dst = smem + SM_A + tid * (AP * 2) + 108 * 2;
            #pragma unroll
            for (int i = 0; i < 18; i++) {
                int k0 = 108 + 2 * i;
                float lo = (k0 <= 129) ? e[k0 - 108] : 0.0f;
                float hi = (k0 + 1 <= 129) ? e[k0 + 1 - 108] : 0.0f;
                __half2 h = __floats2half2_rn(lo, hi);
                *(uint32_t*)(dst + i * 4) = *(uint32_t*)&h;
            }
        }
        __syncthreads();   // S1: A ready (also orders H(t) reads vs H(t+1) writes)

        // ======== GEMM1: H = act(A @ W1^T), 4 acc chains/warp (t x k-parity) ========
        {
            uint32_t Af[2][9][4];
            const uint32_t a_base = su + SM_A + (uint32_t)(mw * 32 + a_row) * (AP * 2) + (uint32_t)a_koff * 2;
            #pragma unroll
            for (int t = 0; t < 2; t++)
                #pragma unroll
                for (int s = 0; s < 9; s++)
                    ldm_x4(Af[t][s][0], Af[t][s][1], Af[t][s][2], Af[t][s][3],
                           a_base + (uint32_t)t * 16 * (AP * 2) + (uint32_t)s * 32);

            const uint32_t b_base = su + SM_W1 + (uint32_t)(nw * 64 + b_row) * (AP * 2) + (uint32_t)b_koff * 2;
            #pragma unroll
            for (int jt = 0; jt < 8; jt++) {
                float acc[2][2][4] = {{{0,0,0,0},{0,0,0,0}},{{0,0,0,0},{0,0,0,0}}};
                #pragma unroll
                for (int s = 0; s < 9; s++) {
                    uint32_t b0, b1v;
                    ldm_x2(b0, b1v, b_base + (uint32_t)jt * 8 * (AP * 2) + (uint32_t)s * 32);
                    mma16816(acc[0][s & 1], Af[0][s], b0, b1v);
                    mma16816(acc[1][s & 1], Af[1][s], b0, b1v);
                }
                #pragma unroll
                for (int t = 0; t < 2; t++) {
                    float c0 = acc[t][0][0] + acc[t][1][0];
                    float c1 = acc[t][0][1] + acc[t][1][1];
                    float c2 = acc[t][0][2] + acc[t][1][2];
                    float c3 = acc[t][0][3] + acc[t][1][3];
                    __half2 hlo = __floats2half2_rn(actf(c0), actf(c1));
                    __half2 hhi = __floats2half2_rn(actf(c2), actf(c3));
                    char* hp0 = smem + SM_H + (mw * 32 + t * 16 + g) * (HP * 2)
                              + (nw * 64 + jt * 8 + tq * 2) * 2;
                    *(uint32_t*)hp0 = *(uint32_t*)&hlo;
                    *(uint32_t*)(hp0 + 8 * (HP * 2)) = *(uint32_t*)&hhi;
                }
            }
        }
        __syncthreads();   // S2: H ready (also ends all A reads before next gather)

        // ======== GEMM2: out = H @ W2^T + b2, 2 acc chains per (t,j) ========
        {
            const uint32_t h_base = su + SM_H + (uint32_t)(mw * 32 + a_row) * (HP * 2) + (uint32_t)a_koff * 2;
            const uint32_t w2_base = su + SM_W2 + (uint32_t)b_row * (HP * 2) + (uint32_t)b_koff * 2;
            #pragma unroll 1
            for (int t = 0; t < 2; t++) {
                uint32_t Hf[16][4];
                #pragma unroll
                for (int s = 0; s < 16; s++)
                    ldm_x4(Hf[s][0], Hf[s][1], Hf[s][2], Hf[s][3],
                           h_base + (uint32_t)t * 16 * (HP * 2) + (uint32_t)s * 32);
                #pragma unroll 1
                for (int j5 = 0; j5 < 5; j5++) {
                    const int jt = nw + j5 * 4;
                    if (jt >= 17) break;
                    const int o_base = jt * 8;
                    float aE[4] = {0, 0, 0, 0};
                    float aO[4] = {0, 0, 0, 0};
                    const uint32_t wb = w2_base + (uint32_t)o_base * (HP * 2);
                    #pragma unroll
                    for (int s = 0; s < 16; s++) {
                        uint32_t b0, b1v;
                        ldm_x2(b0, b1v, wb + (uint32_t)s * 32);
                        mma16816((s & 1) ? aO : aE, Hf[s], b0, b1v);
                    }
                    const int oc = o_base + tq * 2;
                    const int pr = pt0 + mw * 32 + t * 16 + g;
                    if (pr < NPTS && oc < OUT_CH) {
                        out[(size_t)pr * OUT_CH + oc] = aE[0] + aO[0] + b2s[oc];
                        if (oc + 1 < OUT_CH)
                            out[(size_t)pr * OUT_CH + oc + 1] = aE[1] + aO[1] + b2s[oc + 1];
                    }
                    if (pr + 8 < NPTS && oc < OUT_CH) {
                        out[(size_t)(pr + 8) * OUT_CH + oc] = aE[2] + aO[2] + b2s[oc];
                        if (oc + 1 < OUT_CH)
                            out[(size_t)(pr + 8) * OUT_CH + oc + 1] = aE[3] + aO[3] + b2s[oc + 1];
                    }
                }
            }
        }
        // no 3rd barrier: next S1 provides the H(t)-read / H(t+1)-write ordering,
        // and gather(t+1) only writes A, which no warp touches after S2.
    }
}

// ---------------- launch ----------------
extern "C" void kernel_launch(void* const* d_in, const int* in_sizes, int n_in,
                              void* d_out, int out_size) {
    const float* xyz    = (const float*)d_in[0];
    const float* planes = (const float*)d_in[1];
    const float* lines  = (const float*)d_in[2];
    const float* w1     = (const float*)d_in[3];
    const float* b1     = (const float*)d_in[4];
    const float* w2     = (const float*)d_in[5];
    const float* b2     = (const float*)d_in[6];
    float* out = (float*)d_out;

    int nsm = 148;
    cudaDeviceGetAttribute(&nsm, cudaDevAttrMultiProcessorCount, 0);

    cudaFuncSetAttribute(tensosdf_main_kernel,
                         cudaFuncAttributeMaxDynamicSharedMemorySize, SM_TOTAL);

    transpose_planes_kernel<<<3 * GRID_D * 10, 256>>>(planes);

    const int prep_total = SDF_DIM * K1 + N2P * K2 + 3 * GRID_D * CPAD;
    prep_small_kernel<<<(prep_total + 255) / 256, 256>>>(w1, b1, w2, lines);

    tensosdf_main_kernel<<<nsm, NTHR, SM_TOTAL>>>(xyz, b2, out);
}

// round 15
// speedup vs baseline: 1.5905x; 1.0141x over previous
#include <cuda_runtime.h>
#include <cuda_fp16.h>
#include <math.h>
#include <stdint.h>

// ---------------- problem constants ----------------
#define NPTS    524288
#define GRID_D  300
#define NCOMP   36
#define CPAD    64        // channel dim padded to 64 halves = 128B (one aligned line per corner)
#define SDF_DIM 256
#define OUT_CH  129
#define K1      144       // GEMM1 K (129 used + pad), 9 k-steps
#define AP      152       // A / W1 smem pitch in halves (304B -> conflict-free ldmatrix)
#define N2P     136       // GEMM2 N padded (129 used), 17 n-tiles of 8
#define K2      256       // GEMM2 K, 16 k-steps
#define HP      264       // H / W2 smem pitch in halves (528B -> conflict-free)
#define TILE_M  64
#define NTILES  (NPTS / TILE_M)   // 8192 exact
#define NTHR    384
#define NCONS   256       // warps 0..7  : GEMM consumers
#define NPROD   128       // warps 8..11 : gather producers

// ---------------- smem layout (bytes) ----------------
#define A_BYTES (TILE_M * AP * 2)             // 19456
#define SM_A0  0
#define SM_A1  (SM_A0 + A_BYTES)              // 19456
#define SM_H   (SM_A1 + A_BYTES)              // 38912  (+33792)
#define SM_W1  (SM_H + TILE_M * HP * 2)       // 72704  (+77824)
#define SM_W2  (SM_W1 + SDF_DIM * AP * 2)     // 150528 (+71808)
#define SM_B2  (SM_W2 + N2P * HP * 2)         // 222336
#define SM_TOTAL (SM_B2 + N2P * 4)            // 222880

// named barriers: 1+b = A(b) full, 3+b = A(b) empty, 5 = consumer-internal
#define BAR_SYNC(id, cnt)   asm volatile("bar.sync %0, %1;"   :: "r"(id), "r"(cnt) : "memory")
#define BAR_ARRIVE(id, cnt) asm volatile("bar.arrive %0, %1;" :: "r"(id), "r"(cnt) : "memory")
#define MEMBAR_CTA()        asm volatile("membar.cta;" ::: "memory")

// ---------------- scratch globals ----------------
__device__ __align__(16) __half g_planesTh[3 * GRID_D * GRID_D * CPAD]; // [p][y][x][c64] fp16 (c>=36 zero)
__device__ __align__(16) __half g_linesTh[3 * GRID_D * CPAD];           // [p][z][c64] fp16 (c>=36 zero)
__device__ __align__(16) __half g_w1h[SDF_DIM * K1];                    // [j][k] (permuted, bias row k=129)
__device__ __align__(16) __half g_w2h[N2P * K2];                        // [o][j] (rows >=129 zero)

// ---------------- PTX helpers (sm_80-era, compile on plain sm_103) ----------------
__device__ __forceinline__ uint32_t smem_to_u32(const void* p) {
    uint32_t a;
    asm("{ .reg .u64 t; cvta.to.shared.u64 t, %1; cvt.u32.u64 %0, t; }" : "=r"(a) : "l"(p));
    return a;
}
__device__ __forceinline__ void ldm_x4(uint32_t& r0, uint32_t& r1, uint32_t& r2, uint32_t& r3, uint32_t addr) {
    asm volatile("ldmatrix.sync.aligned.m8n8.x4.shared.b16 {%0,%1,%2,%3}, [%4];"
                 : "=r"(r0), "=r"(r1), "=r"(r2), "=r"(r3) : "r"(addr));
}
__device__ __forceinline__ void ldm_x2(uint32_t& r0, uint32_t& r1, uint32_t addr) {
    asm volatile("ldmatrix.sync.aligned.m8n8.x2.shared.b16 {%0,%1}, [%2];"
                 : "=r"(r0), "=r"(r1) : "r"(addr));
}
__device__ __forceinline__ void mma16816(float* c, const uint32_t* a, uint32_t b0, uint32_t b1) {
    asm volatile("mma.sync.aligned.m16n8k16.row.col.f32.f16.f16.f32 "
                 "{%0,%1,%2,%3}, {%4,%5,%6,%7}, {%8,%9}, {%0,%1,%2,%3};"
                 : "+f"(c[0]), "+f"(c[1]), "+f"(c[2]), "+f"(c[3])
                 : "r"(a[0]), "r"(a[1]), "r"(a[2]), "r"(a[3]), "r"(b0), "r"(b1));
}

// ---------------- preprocess: planes -> fp16 [3][300][300][64] (vectorized stores) ----------------
__global__ void transpose_planes_kernel(const float* __restrict__ planes) {
    int b = blockIdx.x;
    int xt = b % 10;
    int rest = b / 10;
    int y = rest % GRID_D;
    int p = rest / GRID_D;
    int x0 = xt * 32;
    __shared__ float tile[NCOMP][33];
    for (int idx = threadIdx.x; idx < NCOMP * 32; idx += blockDim.x) {
        int c = idx >> 5, xx = idx & 31;
        if (x0 + xx < GRID_D)
            tile[c][xx] = planes[((p * NCOMP + c) * GRID_D + y) * GRID_D + x0 + xx];
    }
    __syncthreads();
    {
        int xx = threadIdx.x >> 3;
        int cg = threadIdx.x & 7;
        if (x0 + xx < GRID_D) {
            union { uint4 u; __half h[8]; } v;
            #pragma unroll
            for (int i = 0; i < 8; i++) {
                int c = cg * 8 + i;
                v.h[i] = __float2half_rn((c < NCOMP) ? tile[c][xx] : 0.0f);
            }
            *(uint4*)(g_planesTh + ((size_t)(p * GRID_D + y) * GRID_D + (x0 + xx)) * CPAD + cg * 8) = v.u;
        }
    }
}

// ---------------- preprocess: fp16 weights (permuted, bias-folded) + fp16 lines ----------------
// A channel order: k 0..107 = feat (orig mlp_in 21..128), k 108..128 = embed (orig 0..20),
//                  k 129 = bias row (A=1, W1=b1), k 130..143 = 0.
__global__ void prep_small_kernel(const float* __restrict__ w1, const float* __restrict__ b1,
                                  const float* __restrict__ w2,
                                  const float* __restrict__ lines) {
    int i = blockIdx.x * blockDim.x + threadIdx.x;
    const int W1N = SDF_DIM * K1;        // 36864
    const int W2N = N2P * K2;            // 34816
    const int LNT = 3 * GRID_D * CPAD;   // 57600
    if (i < W1N) {
        int j = i / K1, k = i % K1;
        float v = 0.0f;
        if (k < 108)       v = w1[j * OUT_CH + 21 + k];
        else if (k < 129)  v = w1[j * OUT_CH + (k - 108)];
        else if (k == 129) v = b1[j];
        g_w1h[i] = __float2half_rn(v);
    } else if (i < W1N + W2N) {
        int t = i - W1N;
        int o = t / K2, j = t % K2;
        g_w2h[t] = __float2half_rn((o < OUT_CH) ? w2[o * SDF_DIM + j] : 0.0f);
    } else if (i < W1N + W2N + LNT) {
        int t = i - W1N - W2N;
        int c = t % CPAD;
        int z = (t / CPAD) % GRID_D;
        int p = t / (CPAD * GRID_D);
        g_linesTh[t] = __float2half_rn((c < NCOMP) ? lines[(p * NCOMP + c) * GRID_D + z] : 0.0f);
    }
}

// ---------------- activation: softplus(100u)/100 ----------------
__device__ __forceinline__ float actf(float u) {
    float t = 100.0f * u;
    return (fmaxf(t, 0.0f) + __logf(1.0f + __expf(-fabsf(t)))) * 0.01f;
}

union U4H { uint4 u; __half2 h[4]; };

// ---------------- persistent warp-specialized kernel ----------------
__global__ __launch_bounds__(NTHR)
void tensosdf_main_kernel(const float* __restrict__ xyz,
                          const float* __restrict__ b2,
                          float* __restrict__ out) {
    extern __shared__ char smem[];
    const uint32_t su = smem_to_u32(smem);
    const int tid  = threadIdx.x;
    const int wid  = tid >> 5;
    const int lane = tid & 31;
    float* b2s = (float*)(smem + SM_B2);

    // ---- stage weights into smem once per CTA (all threads) ----
    {
        __half* sW1 = (__half*)(smem + SM_W1);
        __half* sW2 = (__half*)(smem + SM_W2);
        for (int i = tid; i < SDF_DIM * K1; i += NTHR) {
            int j = i / K1, k = i % K1;
            sW1[j * AP + k] = g_w1h[i];
        }
        for (int i = tid; i < N2P * K2; i += NTHR) {
            int o = i >> 8, j = i & 255;
            sW2[o * HP + j] = g_w2h[i];
        }
        if (tid < N2P) b2s[tid] = (tid < OUT_CH) ? b2[tid] : 0.0f;
    }
    __syncthreads();   // only use of bar0; roles never re-join

    if (wid >= 8) {
        // ================= PRODUCER: gather + embed into A(b) =================
        const int pw = wid - 8;          // 0..3
        const int lc = lane & 7;         // 8-channel chunk within corner line
        const int kt = lane >> 3;        // task slot within round
        const int ptid = tid - NCONS;    // 0..127

        int it = 0;
        for (int tile = blockIdx.x; tile < NTILES; tile += gridDim.x, it++) {
            const int b = it & 1;
            const int pt0 = tile * TILE_M;
            if (it >= 2) BAR_SYNC(3 + b, NTHR);   // wait A(b) empty
            char* Ab = smem + (b ? SM_A1 : SM_A0);

            #pragma unroll
            for (int r = 0; r < 12; r++) {
                const int T = pw * 48 + r * 4 + kt;   // 0..191
                const int point = T / 3;
                const int pl    = T - point * 3;
                if (lc < 5) {
                    int gp = pt0 + point;
                    float x = xyz[gp * 3 + 0];
                    float y = xyz[gp * 3 + 1];
                    float z = xyz[gp * 3 + 2];
                    float sx, sy, sz;
                    if (pl == 0)      { sx = x; sy = y; sz = z; }
                    else if (pl == 1) { sx = x; sy = z; sz = y; }
                    else              { sx = y; sy = z; sz = x; }
                    const float HALF = 0.5f * (GRID_D - 1);
                    float fx = (sx + 1.0f) * HALF;
                    float fy = (sy + 1.0f) * HALF;
                    float fz = (sz + 1.0f) * HALF;
                    int x0 = min(max((int)floorf(fx), 0), GRID_D - 2);
                    int y0 = min(max((int)floorf(fy), 0), GRID_D - 2);
                    int z0 = min(max((int)floorf(fz), 0), GRID_D - 2);
                    float tx = fx - (float)x0;
                    float ty = fy - (float)y0;
                    float tz = fz - (float)z0;
                    float w00 = (1.0f - tx) * (1.0f - ty);
                    float w01 = tx * (1.0f - ty);
                    float w10 = (1.0f - tx) * ty;
                    float w11 = tx * ty;

                    const __half* P = g_planesTh + ((size_t)(pl * GRID_D + y0) * GRID_D + x0) * CPAD + lc * 8;
                    const __half* L = g_linesTh + ((size_t)(pl * GRID_D + z0)) * CPAD + lc * 8;
                    U4H v00, v01, v10, v11, l0v, l1v;
                    v00.u = *(const uint4*)(P);
                    v01.u = *(const uint4*)(P + CPAD);
                    v10.u = *(const uint4*)(P + GRID_D * CPAD);
                    v11.u = *(const uint4*)(P + GRID_D * CPAD + CPAD);
                    l0v.u = *(const uint4*)(L);
                    l1v.u = *(const uint4*)(L + CPAD);

                    uint32_t res[4];
                    #pragma unroll
                    for (int i = 0; i < 4; i++) {
                        float2 a00 = __half22float2(v00.h[i]);
                        float2 a01 = __half22float2(v01.h[i]);
                        float2 a10 = __half22float2(v10.h[i]);
                        float2 a11 = __half22float2(v11.h[i]);
                        float2 b0  = __half22float2(l0v.h[i]);
                        float2 b1  = __half22float2(l1v.h[i]);
                        float ra = (a00.x * w00 + a01.x * w01 + a10.x * w10 + a11.x * w11)
                                 * (b0.x + (b1.x - b0.x) * tz);
                        float rb = (a00.y * w00 + a01.y * w01 + a10.y * w10 + a11.y * w11)
                                 * (b0.y + (b1.y - b0.y) * tz);
                        __half2 hh = __floats2half2_rn(ra, rb);
                        res[i] = *(uint32_t*)&hh;
                    }
                    char* dst = Ab + point * (AP * 2) + (pl * NCOMP + lc * 8) * 2;
                    uint2 lo; lo.x = res[0]; lo.y = res[1];
                    *(uint2*)dst = lo;
                    if (lc < 4) {
                        uint2 hi; hi.x = res[2]; hi.y = res[3];
                        *(uint2*)(dst + 8) = hi;
                    }
                }
            }
            // embed: one point per thread (first 64 producer threads)
            if (ptid < TILE_M) {
                int gp = pt0 + ptid;
                float vx = xyz[gp * 3 + 0];
                float vy = xyz[gp * 3 + 1];
                float vz = xyz[gp * 3 + 2];
                float e[22];
                e[0] = vx; e[1] = vy; e[2] = vz;
                #pragma unroll
                for (int d = 0; d < 3; d++) {
                    float v = (d == 0) ? vx : (d == 1) ? vy : vz;
                    #pragma unroll
                    for (int f = 0; f < 3; f++) {
                        float s, c;
                        sincosf(v * (float)(1 << f), &s, &c);
                        e[3 + d * 3 + f]  = s;
                        e[12 + d * 3 + f] = c;
                    }
                }
                e[21] = 1.0f;  // bias row at k=129
                char* dst = Ab + ptid * (AP * 2) + 108 * 2;
                #pragma unroll
                for (int i = 0; i < 18; i++) {
                    int k0 = 108 + 2 * i;
                    float lo = (k0 <= 129) ? e[k0 - 108] : 0.0f;
                    float hi = (k0 + 1 <= 129) ? e[k0 + 1 - 108] : 0.0f;
                    __half2 h = __floats2half2_rn(lo, hi);
                    *(uint32_t*)(dst + i * 4) = *(uint32_t*)&h;
                }
            }
            MEMBAR_CTA();
            BAR_ARRIVE(1 + b, NTHR);   // A(b) full
        }
    } else {
        // ================= CONSUMER: GEMM1 -> act -> GEMM2 =================
        const int mw = wid >> 2;   // 0..1 : 32-point m-slab
        const int nw = wid & 3;    // 0..3 : n-slab
        const int g  = lane >> 2;
        const int tq = lane & 3;
        const int a_row  = (lane & 15);
        const int a_koff = (lane >> 4) * 8;
        const int b_row  = (lane & 7);
        const int b_koff = ((lane >> 3) & 1) * 8;

        int it = 0;
        for (int tile = blockIdx.x; tile < NTILES; tile += gridDim.x, it++) {
            const int b = it & 1;
            const int pt0 = tile * TILE_M;
            BAR_SYNC(1 + b, NTHR);   // wait A(b) full
            const uint32_t suA = su + (b ? SM_A1 : SM_A0);

            // ---- GEMM1: H = act(A @ W1^T), 4 acc chains/warp ----
            {
                uint32_t Af[2][9][4];
                const uint32_t a_base = suA + (uint32_t)(mw * 32 + a_row) * (AP * 2) + (uint32_t)a_koff * 2;
                #pragma unroll
                for (int t = 0; t < 2; t++)
                    #pragma unroll
                    for (int s = 0; s < 9; s++)
                        ldm_x4(Af[t][s][0], Af[t][s][1], Af[t][s][2], Af[t][s][3],
                               a_base + (uint32_t)t * 16 * (AP * 2) + (uint32_t)s * 32);

                const uint32_t b_base = su + SM_W1 + (uint32_t)(nw * 64 + b_row) * (AP * 2) + (uint32_t)b_koff * 2;
                float accAll[8][2][2][4];   // [jt][t][parity][4]
                #pragma unroll
                for (int jt = 0; jt < 8; jt++) {
                    float (*acc)[2][4] = accAll[jt];
                    #pragma unroll
                    for (int t = 0; t < 2; t++)
                        #pragma unroll
                        for (int pz = 0; pz < 2; pz++)
                            { acc[t][pz][0]=0; acc[t][pz][1]=0; acc[t][pz][2]=0; acc[t][pz][3]=0; }
                    #pragma unroll
                    for (int s = 0; s < 9; s++) {
                        uint32_t b0, b1v;
                        ldm_x2(b0, b1v, b_base + (uint32_t)jt * 8 * (AP * 2) + (uint32_t)s * 32);
                        mma16816(acc[0][s & 1], Af[0][s], b0, b1v);
                        mma16816(acc[1][s & 1], Af[1][s], b0, b1v);
                    }
                }
                BAR_ARRIVE(3 + b, NTHR);   // Af consumed -> A(b) empty

                #pragma unroll
                for (int jt = 0; jt < 8; jt++) {
                    #pragma unroll
                    for (int t = 0; t < 2; t++) {
                        float c0 = accAll[jt][t][0][0] + accAll[jt][t][1][0];
                        float c1 = accAll[jt][t][0][1] + accAll[jt][t][1][1];
                        float c2 = accAll[jt][t][0][2] + accAll[jt][t][1][2];
                        float c3 = accAll[jt][t][0][3] + accAll[jt][t][1][3];
                        __half2 hlo = __floats2half2_rn(actf(c0), actf(c1));
                        __half2 hhi = __floats2half2_rn(actf(c2), actf(c3));
                        char* hp0 = smem + SM_H + (mw * 32 + t * 16 + g) * (HP * 2)
                                  + (nw * 64 + jt * 8 + tq * 2) * 2;
                        *(uint32_t*)hp0 = *(uint32_t*)&hlo;
                        *(uint32_t*)(hp0 + 8 * (HP * 2)) = *(uint32_t*)&hhi;
                    }
                }
            }
            BAR_SYNC(5, NCONS);   // H ready (consumer-only)

            // ---- GEMM2: out = H @ W2^T + b2 ----
            {
                const uint32_t h_base = su + SM_H + (uint32_t)(mw * 32 + a_row) * (HP * 2) + (uint32_t)a_koff * 2;
                const uint32_t w2_base = su + SM_W2 + (uint32_t)b_row * (HP * 2) + (uint32_t)b_koff * 2;
                #pragma unroll 1
                for (int t = 0; t < 2; t++) {
                    uint32_t Hf[16][4];
                    #pragma unroll
                    for (int s = 0; s < 16; s++)
                        ldm_x4(Hf[s][0], Hf[s][1], Hf[s][2], Hf[s][3],
                               h_base + (uint32_t)t * 16 * (HP * 2) + (uint32_t)s * 32);
                    #pragma unroll 1
                    for (int j5 = 0; j5 < 5; j5++) {
                        const int jt = nw + j5 * 4;
                        if (jt >= 17) break;
                        const int o_base = jt * 8;
                        float aE[4] = {0, 0, 0, 0};
                        float aO[4] = {0, 0, 0, 0};
                        const uint32_t wb = w2_base + (uint32_t)o_base * (HP * 2);
                        #pragma unroll
                        for (int s = 0; s < 16; s++) {
                            uint32_t b0, b1v;
                            ldm_x2(b0, b1v, wb + (uint32_t)s * 32);
                            mma16816((s & 1) ? aO : aE, Hf[s], b0, b1v);
                        }
                        const int oc = o_base + tq * 2;
                        const int pr = pt0 + mw * 32 + t * 16 + g;
                        if (oc < OUT_CH) {
                            out[(size_t)pr * OUT_CH + oc]       = aE[0] + aO[0] + b2s[oc];
                            out[(size_t)(pr + 8) * OUT_CH + oc] = aE[2] + aO[2] + b2s[oc];
                            if (oc + 1 < OUT_CH) {
                                out[(size_t)pr * OUT_CH + oc + 1]       = aE[1] + aO[1] + b2s[oc + 1];
                                out[(size_t)(pr + 8) * OUT_CH + oc + 1] = aE[3] + aO[3] + b2s[oc + 1];
                            }
                        }
                    }
                }
            }
            BAR_SYNC(5, NCONS);   // H consumed before next tile's H writes
        }
    }
}

// ---------------- launch ----------------
extern "C" void kernel_launch(void* const* d_in, const int* in_sizes, int n_in,
                              void* d_out, int out_size) {
    const float* xyz    = (const float*)d_in[0];
    const float* planes = (const float*)d_in[1];
    const float* lines  = (const float*)d_in[2];
    const float* w1     = (const float*)d_in[3];
    const float* b1     = (const float*)d_in[4];
    const float* w2     = (const float*)d_in[5];
    const float* b2     = (const float*)d_in[6];
    float* out = (float*)d_out;

    int nsm = 148;
    cudaDeviceGetAttribute(&nsm, cudaDevAttrMultiProcessorCount, 0);

    cudaFuncSetAttribute(tensosdf_main_kernel,
                         cudaFuncAttributeMaxDynamicSharedMemorySize, SM_TOTAL);

    transpose_planes_kernel<<<3 * GRID_D * 10, 256>>>(planes);

    const int prep_total = SDF_DIM * K1 + N2P * K2 + 3 * GRID_D * CPAD;
    prep_small_kernel<<<(prep_total + 255) / 256, 256>>>(w1, b1, w2, lines);

    tensosdf_main_kernel<<<nsm, NTHR, SM_TOTAL>>>(xyz, b2, out);
}

// round 16
// speedup vs baseline: 1.6399x; 1.0310x over previous
#include <cuda_runtime.h>
#include <cuda_fp16.h>
#include <math.h>
#include <stdint.h>

// ---------------- problem constants ----------------
#define NPTS    524288
#define GRID_D  300
#define NCOMP   36
#define CPAD    64        // channel dim padded to 64 halves = 128B (one aligned line per corner)
#define SDF_DIM 256
#define OUT_CH  129
#define K1      144       // GEMM1 K (129 used + pad), 9 k-steps
#define AP      152       // A / W1 smem pitch in halves (304B -> conflict-free ldmatrix)
#define N2P     136       // GEMM2 N padded (129 used), 17 n-tiles of 8
#define K2      256       // GEMM2 K, 16 k-steps
#define HP      264       // H / W2 smem pitch in halves (528B -> conflict-free)
#define TILE_M  64
#define NTILES  (NPTS / TILE_M)   // 8192 exact
#define NTHR    384
#define NCONS   256       // warps 0..7  : GEMM consumers
#define NPROD   128       // warps 8..11 : gather producers

// ---------------- smem layout (bytes) ----------------
#define A_BYTES (TILE_M * AP * 2)             // 19456
#define SM_A0  0
#define SM_A1  (SM_A0 + A_BYTES)              // 19456
#define SM_H   (SM_A1 + A_BYTES)              // 38912  (+33792)
#define SM_W1  (SM_H + TILE_M * HP * 2)       // 72704  (+77824)
#define SM_W2  (SM_W1 + SDF_DIM * AP * 2)     // 150528 (+71808)
#define SM_B2  (SM_W2 + N2P * HP * 2)         // 222336
#define SM_TOTAL (SM_B2 + N2P * 4)            // 222880

// named barriers: 1+b = A(b) full, 3+b = A(b) empty, 5 = consumer-internal
#define BAR_SYNC(id, cnt)   asm volatile("bar.sync %0, %1;"   :: "r"(id), "r"(cnt) : "memory")
#define BAR_ARRIVE(id, cnt) asm volatile("bar.arrive %0, %1;" :: "r"(id), "r"(cnt) : "memory")
#define MEMBAR_CTA()        asm volatile("membar.cta;" ::: "memory")

// ---------------- scratch globals ----------------
__device__ __align__(16) __half g_planesTh[3 * GRID_D * GRID_D * CPAD]; // [p][y][x][c64] fp16 (c>=36 zero)
__device__ __align__(16) __half g_linesTh[3 * GRID_D * CPAD];           // [p][z][c64] fp16 (c>=36 zero)
__device__ __align__(16) __half g_w1h[SDF_DIM * K1];                    // [j][k] (permuted, bias row k=129)
__device__ __align__(16) __half g_w2h[N2P * K2];                        // [o][j] (rows >=129 zero)

// ---------------- PTX helpers (sm_80-era, compile on plain sm_103) ----------------
__device__ __forceinline__ uint32_t smem_to_u32(const void* p) {
    uint32_t a;
    asm("{ .reg .u64 t; cvta.to.shared.u64 t, %1; cvt.u32.u64 %0, t; }" : "=r"(a) : "l"(p));
    return a;
}
__device__ __forceinline__ void ldm_x4(uint32_t& r0, uint32_t& r1, uint32_t& r2, uint32_t& r3, uint32_t addr) {
    asm volatile("ldmatrix.sync.aligned.m8n8.x4.shared.b16 {%0,%1,%2,%3}, [%4];"
                 : "=r"(r0), "=r"(r1), "=r"(r2), "=r"(r3) : "r"(addr));
}
__device__ __forceinline__ void ldm_x2(uint32_t& r0, uint32_t& r1, uint32_t addr) {
    asm volatile("ldmatrix.sync.aligned.m8n8.x2.shared.b16 {%0,%1}, [%2];"
                 : "=r"(r0), "=r"(r1) : "r"(addr));
}
__device__ __forceinline__ void mma16816(float* c, const uint32_t* a, uint32_t b0, uint32_t b1) {
    asm volatile("mma.sync.aligned.m16n8k16.row.col.f32.f16.f16.f32 "
                 "{%0,%1,%2,%3}, {%4,%5,%6,%7}, {%8,%9}, {%0,%1,%2,%3};"
                 : "+f"(c[0]), "+f"(c[1]), "+f"(c[2]), "+f"(c[3])
                 : "r"(a[0]), "r"(a[1]), "r"(a[2]), "r"(a[3]), "r"(b0), "r"(b1));
}

// ---------------- preprocess: planes -> fp16 [3][300][300][64] (vectorized stores) ----------------
__global__ void transpose_planes_kernel(const float* __restrict__ planes) {
    int b = blockIdx.x;
    int xt = b % 10;
    int rest = b / 10;
    int y = rest % GRID_D;
    int p = rest / GRID_D;
    int x0 = xt * 32;
    __shared__ float tile[NCOMP][33];
    for (int idx = threadIdx.x; idx < NCOMP * 32; idx += blockDim.x) {
        int c = idx >> 5, xx = idx & 31;
        if (x0 + xx < GRID_D)
            tile[c][xx] = planes[((p * NCOMP + c) * GRID_D + y) * GRID_D + x0 + xx];
    }
    __syncthreads();
    {
        int xx = threadIdx.x >> 3;
        int cg = threadIdx.x & 7;
        if (x0 + xx < GRID_D) {
            union { uint4 u; __half h[8]; } v;
            #pragma unroll
            for (int i = 0; i < 8; i++) {
                int c = cg * 8 + i;
                v.h[i] = __float2half_rn((c < NCOMP) ? tile[c][xx] : 0.0f);
            }
            *(uint4*)(g_planesTh + ((size_t)(p * GRID_D + y) * GRID_D + (x0 + xx)) * CPAD + cg * 8) = v.u;
        }
    }
}

// ---------------- preprocess: fp16 weights (permuted, bias-folded) + fp16 lines ----------------
// A channel order: k 0..107 = feat (orig mlp_in 21..128), k 108..128 = embed (orig 0..20),
//                  k 129 = bias row (A=1, W1=b1), k 130..143 = 0.
__global__ void prep_small_kernel(const float* __restrict__ w1, const float* __restrict__ b1,
                                  const float* __restrict__ w2,
                                  const float* __restrict__ lines) {
    int i = blockIdx.x * blockDim.x + threadIdx.x;
    const int W1N = SDF_DIM * K1;        // 36864
    const int W2N = N2P * K2;            // 34816
    const int LNT = 3 * GRID_D * CPAD;   // 57600
    if (i < W1N) {
        int j = i / K1, k = i % K1;
        float v = 0.0f;
        if (k < 108)       v = w1[j * OUT_CH + 21 + k];
        else if (k < 129)  v = w1[j * OUT_CH + (k - 108)];
        else if (k == 129) v = b1[j];
        g_w1h[i] = __float2half_rn(v);
    } else if (i < W1N + W2N) {
        int t = i - W1N;
        int o = t / K2, j = t % K2;
        g_w2h[t] = __float2half_rn((o < OUT_CH) ? w2[o * SDF_DIM + j] : 0.0f);
    } else if (i < W1N + W2N + LNT) {
        int t = i - W1N - W2N;
        int c = t % CPAD;
        int z = (t / CPAD) % GRID_D;
        int p = t / (CPAD * GRID_D);
        g_linesTh[t] = __float2half_rn((c < NCOMP) ? lines[(p * NCOMP + c) * GRID_D + z] : 0.0f);
    }
}

// ---------------- activation: softplus(100u)/100 ----------------
__device__ __forceinline__ float actf(float u) {
    float t = 100.0f * u;
    return (fmaxf(t, 0.0f) + __logf(1.0f + __expf(-fabsf(t)))) * 0.01f;
}

union U4H { uint4 u; __half2 h[4]; };

// ---------------- persistent warp-specialized kernel ----------------
__global__ __launch_bounds__(NTHR)
void tensosdf_main_kernel(const float* __restrict__ xyz,
                          const float* __restrict__ b2,
                          float* __restrict__ out) {
    extern __shared__ char smem[];
    const uint32_t su = smem_to_u32(smem);
    const int tid  = threadIdx.x;
    const int wid  = tid >> 5;
    const int lane = tid & 31;
    float* b2s = (float*)(smem + SM_B2);

    // ---- stage weights into smem once per CTA (all threads) ----
    {
        __half* sW1 = (__half*)(smem + SM_W1);
        __half* sW2 = (__half*)(smem + SM_W2);
        for (int i = tid; i < SDF_DIM * K1; i += NTHR) {
            int j = i / K1, k = i % K1;
            sW1[j * AP + k] = g_w1h[i];
        }
        for (int i = tid; i < N2P * K2; i += NTHR) {
            int o = i >> 8, j = i & 255;
            sW2[o * HP + j] = g_w2h[i];
        }
        if (tid < N2P) b2s[tid] = (tid < OUT_CH) ? b2[tid] : 0.0f;
    }
    __syncthreads();   // only use of bar0; roles never re-join

    if (wid >= 8) {
        // ================= PRODUCER: gather + embed into A(b) =================
        const int pw = wid - 8;          // 0..3
        const int lc = lane & 7;         // 8-channel chunk within corner line
        const int kt = lane >> 3;        // task slot within round
        const int ptid = tid - NCONS;    // 0..127

        int it = 0;
        for (int tile = blockIdx.x; tile < NTILES; tile += gridDim.x, it++) {
            const int b = it & 1;
            const int pt0 = tile * TILE_M;
            if (it >= 2) BAR_SYNC(3 + b, NTHR);   // wait A(b) empty
            char* Ab = smem + (b ? SM_A1 : SM_A0);

            #pragma unroll
            for (int r = 0; r < 12; r++) {
                const int T = pw * 48 + r * 4 + kt;   // 0..191
                const int point = T / 3;
                const int pl    = T - point * 3;
                if (lc < 5) {
                    int gp = pt0 + point;
                    float x = xyz[gp * 3 + 0];
                    float y = xyz[gp * 3 + 1];
                    float z = xyz[gp * 3 + 2];
                    float sx, sy, sz;
                    if (pl == 0)      { sx = x; sy = y; sz = z; }
                    else if (pl == 1) { sx = x; sy = z; sz = y; }
                    else              { sx = y; sy = z; sz = x; }
                    const float HALF = 0.5f * (GRID_D - 1);
                    float fx = (sx + 1.0f) * HALF;
                    float fy = (sy + 1.0f) * HALF;
                    float fz = (sz + 1.0f) * HALF;
                    int x0 = min(max((int)floorf(fx), 0), GRID_D - 2);
                    int y0 = min(max((int)floorf(fy), 0), GRID_D - 2);
                    int z0 = min(max((int)floorf(fz), 0), GRID_D - 2);
                    float tx = fx - (float)x0;
                    float ty = fy - (float)y0;
                    float tz = fz - (float)z0;
                    float w00 = (1.0f - tx) * (1.0f - ty);
                    float w01 = tx * (1.0f - ty);
                    float w10 = (1.0f - tx) * ty;
                    float w11 = tx * ty;

                    const __half* P = g_planesTh + ((size_t)(pl * GRID_D + y0) * GRID_D + x0) * CPAD + lc * 8;
                    const __half* L = g_linesTh + ((size_t)(pl * GRID_D + z0)) * CPAD + lc * 8;
                    U4H v00, v01, v10, v11, l0v, l1v;
                    v00.u = *(const uint4*)(P);
                    v01.u = *(const uint4*)(P + CPAD);
                    v10.u = *(const uint4*)(P + GRID_D * CPAD);
                    v11.u = *(const uint4*)(P + GRID_D * CPAD + CPAD);
                    l0v.u = *(const uint4*)(L);
                    l1v.u = *(const uint4*)(L + CPAD);

                    uint32_t res[4];
                    #pragma unroll
                    for (int i = 0; i < 4; i++) {
                        float2 a00 = __half22float2(v00.h[i]);
                        float2 a01 = __half22float2(v01.h[i]);
                        float2 a10 = __half22float2(v10.h[i]);
                        float2 a11 = __half22float2(v11.h[i]);
                        float2 b0  = __half22float2(l0v.h[i]);
                        float2 b1  = __half22float2(l1v.h[i]);
                        float ra = (a00.x * w00 + a01.x * w01 + a10.x * w10 + a11.x * w11)
                                 * (b0.x + (b1.x - b0.x) * tz);
                        float rb = (a00.y * w00 + a01.y * w01 + a10.y * w10 + a11.y * w11)
                                 * (b0.y + (b1.y - b0.y) * tz);
                        __half2 hh = __floats2half2_rn(ra, rb);
                        res[i] = *(uint32_t*)&hh;
                    }
                    char* dst = Ab + point * (AP * 2) + (pl * NCOMP + lc * 8) * 2;
                    uint2 lo; lo.x = res[0]; lo.y = res[1];
                    *(uint2*)dst = lo;
                    if (lc < 4) {
                        uint2 hi; hi.x = res[2]; hi.y = res[3];
                        *(uint2*)(dst + 8) = hi;
                    }
                }
            }
            // embed: one point per thread (first 64 producer threads)
            if (ptid < TILE_M) {
                int gp = pt0 + ptid;
                float vx = xyz[gp * 3 + 0];
                float vy = xyz[gp * 3 + 1];
                float vz = xyz[gp * 3 + 2];
                float e[22];
                e[0] = vx; e[1] = vy; e[2] = vz;
                #pragma unroll
                for (int d = 0; d < 3; d++) {
                    float v = (d == 0) ? vx : (d == 1) ? vy : vz;
                    #pragma unroll
                    for (int f = 0; f < 3; f++) {
                        float s, c;
                        sincosf(v * (float)(1 << f), &s, &c);
                        e[3 + d * 3 + f]  = s;
                        e[12 + d * 3 + f] = c;
                    }
                }
                e[21] = 1.0f;  // bias row at k=129
                char* dst = Ab + ptid * (AP * 2) + 108 * 2;
                #pragma unroll
                for (int i = 0; i < 18; i++) {
                    int k0 = 108 + 2 * i;
                    float lo = (k0 <= 129) ? e[k0 - 108] : 0.0f;
                    float hi = (k0 + 1 <= 129) ? e[k0 + 1 - 108] : 0.0f;
                    __half2 h = __floats2half2_rn(lo, hi);
                    *(uint32_t*)(dst + i * 4) = *(uint32_t*)&h;
                }
            }
            MEMBAR_CTA();
            BAR_ARRIVE(1 + b, NTHR);   // A(b) full
        }
    } else {
        // ================= CONSUMER: GEMM1 -> act -> GEMM2 =================
        const int mw = wid >> 2;   // 0..1 : 32-point m-slab
        const int nw = wid & 3;    // 0..3 : n-slab
        const int g  = lane >> 2;
        const int tq = lane & 3;
        const int a_row  = (lane & 15);
        const int a_koff = (lane >> 4) * 8;
        const int b_row  = (lane & 7);
        const int b_koff = ((lane >> 3) & 1) * 8;

        int it = 0;
        for (int tile = blockIdx.x; tile < NTILES; tile += gridDim.x, it++) {
            const int b = it & 1;
            const int pt0 = tile * TILE_M;
            BAR_SYNC(1 + b, NTHR);   // wait A(b) full
            const uint32_t suA = su + (b ? SM_A1 : SM_A0);

            // ---- GEMM1: H = act(A @ W1^T), per-jt acc (low reg pressure, no spills) ----
            {
                uint32_t Af[2][9][4];
                const uint32_t a_base = suA + (uint32_t)(mw * 32 + a_row) * (AP * 2) + (uint32_t)a_koff * 2;
                #pragma unroll
                for (int t = 0; t < 2; t++)
                    #pragma unroll
                    for (int s = 0; s < 9; s++)
                        ldm_x4(Af[t][s][0], Af[t][s][1], Af[t][s][2], Af[t][s][3],
                               a_base + (uint32_t)t * 16 * (AP * 2) + (uint32_t)s * 32);

                const uint32_t b_base = su + SM_W1 + (uint32_t)(nw * 64 + b_row) * (AP * 2) + (uint32_t)b_koff * 2;
                #pragma unroll
                for (int jt = 0; jt < 8; jt++) {
                    float acc[2][2][4] = {{{0,0,0,0},{0,0,0,0}},{{0,0,0,0},{0,0,0,0}}};  // [t][parity][4]
                    #pragma unroll
                    for (int s = 0; s < 9; s++) {
                        uint32_t b0, b1v;
                        ldm_x2(b0, b1v, b_base + (uint32_t)jt * 8 * (AP * 2) + (uint32_t)s * 32);
                        mma16816(acc[0][s & 1], Af[0][s], b0, b1v);
                        mma16816(acc[1][s & 1], Af[1][s], b0, b1v);
                    }
                    #pragma unroll
                    for (int t = 0; t < 2; t++) {
                        float c0 = acc[t][0][0] + acc[t][1][0];
                        float c1 = acc[t][0][1] + acc[t][1][1];
                        float c2 = acc[t][0][2] + acc[t][1][2];
                        float c3 = acc[t][0][3] + acc[t][1][3];
                        __half2 hlo = __floats2half2_rn(actf(c0), actf(c1));
                        __half2 hhi = __floats2half2_rn(actf(c2), actf(c3));
                        char* hp0 = smem + SM_H + (mw * 32 + t * 16 + g) * (HP * 2)
                                  + (nw * 64 + jt * 8 + tq * 2) * 2;
                        *(uint32_t*)hp0 = *(uint32_t*)&hlo;
                        *(uint32_t*)(hp0 + 8 * (HP * 2)) = *(uint32_t*)&hhi;
                    }
                }
                BAR_ARRIVE(3 + b, NTHR);   // Af fully consumed -> A(b) empty
            }
            BAR_SYNC(5, NCONS);   // H ready (consumer-only)

            // ---- GEMM2: out = H @ W2^T + b2 ----
            {
                const uint32_t h_base = su + SM_H + (uint32_t)(mw * 32 + a_row) * (HP * 2) + (uint32_t)a_koff * 2;
                const uint32_t w2_base = su + SM_W2 + (uint32_t)b_row * (HP * 2) + (uint32_t)b_koff * 2;
                #pragma unroll 1
                for (int t = 0; t < 2; t++) {
                    uint32_t Hf[16][4];
                    #pragma unroll
                    for (int s = 0; s < 16; s++)
                        ldm_x4(Hf[s][0], Hf[s][1], Hf[s][2], Hf[s][3],
                               h_base + (uint32_t)t * 16 * (HP * 2) + (uint32_t)s * 32);
                    #pragma unroll 1
                    for (int j5 = 0; j5 < 5; j5++) {
                        const int jt = nw + j5 * 4;
                        if (jt >= 17) break;
                        const int o_base = jt * 8;
                        float aE[4] = {0, 0, 0, 0};
                        float aO[4] = {0, 0, 0, 0};
                        const uint32_t wb = w2_base + (uint32_t)o_base * (HP * 2);
                        #pragma unroll
                        for (int s = 0; s < 16; s++) {
                            uint32_t b0, b1v;
                            ldm_x2(b0, b1v, wb + (uint32_t)s * 32);
                            mma16816((s & 1) ? aO : aE, Hf[s], b0, b1v);
                        }
                        const int oc = o_base + tq * 2;
                        const int pr = pt0 + mw * 32 + t * 16 + g;
                        if (oc < OUT_CH) {
                            out[(size_t)pr * OUT_CH + oc]       = aE[0] + aO[0] + b2s[oc];
                            out[(size_t)(pr + 8) * OUT_CH + oc] = aE[2] + aO[2] + b2s[oc];
                            if (oc + 1 < OUT_CH) {
                                out[(size_t)pr * OUT_CH + oc + 1]       = aE[1] + aO[1] + b2s[oc + 1];
                                out[(size_t)(pr + 8) * OUT_CH + oc + 1] = aE[3] + aO[3] + b2s[oc + 1];
                            }
                        }
                    }
                }
            }
            BAR_SYNC(5, NCONS);   // H consumed before next tile's H writes
        }
    }
}

// ---------------- launch ----------------
extern "C" void kernel_launch(void* const* d_in, const int* in_sizes, int n_in,
                              void* d_out, int out_size) {
    const float* xyz    = (const float*)d_in[0];
    const float* planes = (const float*)d_in[1];
    const float* lines  = (const float*)d_in[2];
    const float* w1     = (const float*)d_in[3];
    const float* b1     = (const float*)d_in[4];
    const float* w2     = (const float*)d_in[5];
    const float* b2     = (const float*)d_in[6];
    float* out = (float*)d_out;

    int nsm = 148;
    cudaDeviceGetAttribute(&nsm, cudaDevAttrMultiProcessorCount, 0);

    cudaFuncSetAttribute(tensosdf_main_kernel,
                         cudaFuncAttributeMaxDynamicSharedMemorySize, SM_TOTAL);

    transpose_planes_kernel<<<3 * GRID_D * 10, 256>>>(planes);

    const int prep_total = SDF_DIM * K1 + N2P * K2 + 3 * GRID_D * CPAD;
    prep_small_kernel<<<(prep_total + 255) / 256, 256>>>(w1, b1, w2, lines);

    tensosdf_main_kernel<<<nsm, NTHR, SM_TOTAL>>>(xyz, b2, out);
}